// round 1
// baseline (speedup 1.0000x reference)
#include <cuda_runtime.h>
#include <math.h>

#define BB 2
#define SS 4096
#define NN 4
#define DD 2048
#define ND (NN*DD)            /* 8192  */
#define BND (BB*ND)           /* 16384 */
#define SCHUNK 256
#define ROWS_PER_BLK (SS/SCHUNK)  /* 16 */
#define D4 (DD/4)             /* 512 */
#define LN_EPS 1e-5f
#define SK_EPS 1e-8f

// Scratch (no allocations allowed)
__device__ float g_partial[SCHUNK * BND];   // 16 MB partial LN-mean sums
__device__ float g_hflat[BND];              // H_flat (B, N*D)
__device__ float g_delta[BB * 24];          // raw dots: [post4 | pre4 | res16] per b
__device__ float g_mix[BB * 24];            // final:    [pre4  | post4 | res16] per b

// ---------------------------------------------------------------------------
// K1: per-row LayerNorm + partial sum over S chunk. One block = (chunk, n, b),
// 16 rows of D=2048. Each thread owns 8 elements (two float4 slots).
// ---------------------------------------------------------------------------
__global__ __launch_bounds__(256) void k1_ln_reduce(const float* __restrict__ H) {
    const int chunk = blockIdx.x, n = blockIdx.y, b = blockIdx.z;
    const int t = threadIdx.x;
    const int warp = t >> 5, lane = t & 31;
    __shared__ float s_w[2][8];
    __shared__ float s_bc[2];

    float a0=0.f,a1=0.f,a2=0.f,a3=0.f,a4=0.f,a5=0.f,a6=0.f,a7=0.f;

    for (int r = 0; r < ROWS_PER_BLK; ++r) {
        int s = chunk * ROWS_PER_BLK + r;
        const float4* row = (const float4*)(H + ((size_t)((b*SS + s)*NN + n)) * DD);
        float4 v0 = row[t];
        float4 v1 = row[t + 256];

        float sm = v0.x+v0.y+v0.z+v0.w + v1.x+v1.y+v1.z+v1.w;
        float sq = v0.x*v0.x+v0.y*v0.y+v0.z*v0.z+v0.w*v0.w
                 + v1.x*v1.x+v1.y*v1.y+v1.z*v1.z+v1.w*v1.w;
        #pragma unroll
        for (int o = 16; o; o >>= 1) {
            sm += __shfl_xor_sync(0xffffffffu, sm, o);
            sq += __shfl_xor_sync(0xffffffffu, sq, o);
        }
        if (lane == 0) { s_w[0][warp] = sm; s_w[1][warp] = sq; }
        __syncthreads();
        if (warp == 0) {
            float aa = (lane < 8) ? s_w[0][lane] : 0.f;
            float cc = (lane < 8) ? s_w[1][lane] : 0.f;
            #pragma unroll
            for (int o = 4; o; o >>= 1) {
                aa += __shfl_xor_sync(0xffffffffu, aa, o);
                cc += __shfl_xor_sync(0xffffffffu, cc, o);
            }
            if (lane == 0) {
                float mu  = aa * (1.f / DD);
                float var = cc * (1.f / DD) - mu * mu;
                s_bc[0] = mu;
                s_bc[1] = rsqrtf(var + LN_EPS);
            }
        }
        __syncthreads();
        float mu = s_bc[0], rstd = s_bc[1];
        a0 += (v0.x - mu) * rstd;  a1 += (v0.y - mu) * rstd;
        a2 += (v0.z - mu) * rstd;  a3 += (v0.w - mu) * rstd;
        a4 += (v1.x - mu) * rstd;  a5 += (v1.y - mu) * rstd;
        a6 += (v1.z - mu) * rstd;  a7 += (v1.w - mu) * rstd;
    }

    float4* p = (float4*)(g_partial + (size_t)chunk * BND + (size_t)(b*NN + n) * DD);
    p[t]       = make_float4(a0, a1, a2, a3);
    p[t + 256] = make_float4(a4, a5, a6, a7);
}

// ---------------------------------------------------------------------------
// K2a: reduce the 256 chunk partials -> H_flat, apply gamma/beta and /S.
// ---------------------------------------------------------------------------
__global__ __launch_bounds__(256) void k2a_reduce(const float* __restrict__ gamma,
                                                  const float* __restrict__ beta) {
    int o = blockIdx.x * 256 + threadIdx.x;   // [0, BND)
    float sum = 0.f;
    #pragma unroll 8
    for (int c = 0; c < SCHUNK; ++c) sum += g_partial[(size_t)c * BND + o];
    int d = o & (DD - 1);
    g_hflat[o] = gamma[d] * (sum * (1.f / SS)) + beta[d];
}

// ---------------------------------------------------------------------------
// K2b: 48 dot products of length 8192. block = (row r in [0,24), batch b).
// ---------------------------------------------------------------------------
__global__ __launch_bounds__(256) void k2b_dots(const float* __restrict__ Wpost,
                                                const float* __restrict__ Wpre,
                                                const float* __restrict__ Wres) {
    const int r = blockIdx.x, b = blockIdx.y;
    const float* w = (r < 4)  ? (Wpost + (size_t)r * ND)
                   : (r < 8)  ? (Wpre  + (size_t)(r - 4) * ND)
                              : (Wres  + (size_t)(r - 8) * ND);
    const float* h = g_hflat + b * ND;
    float sum = 0.f;
    for (int k = threadIdx.x; k < ND; k += 256) sum += h[k] * w[k];

    __shared__ float s_w[8];
    int warp = threadIdx.x >> 5, lane = threadIdx.x & 31;
    #pragma unroll
    for (int o = 16; o; o >>= 1) sum += __shfl_xor_sync(0xffffffffu, sum, o);
    if (lane == 0) s_w[warp] = sum;
    __syncthreads();
    if (threadIdx.x == 0) {
        float t = 0.f;
        #pragma unroll
        for (int i = 0; i < 8; ++i) t += s_w[i];
        g_delta[b * 24 + r] = t;
    }
}

// ---------------------------------------------------------------------------
// K2c: sigmoid gates + H_pre normalize + 4x4 Sinkhorn (20 iters). 1 thread/b.
// ---------------------------------------------------------------------------
__global__ void k2c_small(const float* __restrict__ postb,
                          const float* __restrict__ preb,
                          const float* __restrict__ resb,
                          const float* __restrict__ sp,
                          const float* __restrict__ spr,
                          const float* __restrict__ sr) {
    int b = threadIdx.x;
    if (b >= BB) return;
    const float* dlt = g_delta + b * 24;
    float scp = sp[0], scq = spr[0], scr = sr[0];

    float pre[4], post[4], M[16];
    float psum = 0.f;
    #pragma unroll
    for (int n = 0; n < 4; ++n) {
        post[n] = 1.f / (1.f + expf(-(postb[n] + dlt[n]     * scp)));
        float pv = 1.f / (1.f + expf(-(preb[n] + dlt[4 + n] * scq)));
        pre[n] = pv; psum += pv;
    }
    float inv = 1.f / (psum + SK_EPS);
    #pragma unroll
    for (int n = 0; n < 4; ++n) pre[n] *= inv;

    #pragma unroll
    for (int e = 0; e < 16; ++e) M[e] = expf(resb[e] + dlt[8 + e] * scr);

    for (int it = 0; it < 20; ++it) {
        #pragma unroll
        for (int i = 0; i < 4; ++i) {
            float rs = M[i*4] + M[i*4+1] + M[i*4+2] + M[i*4+3] + SK_EPS;
            float iv = 1.f / rs;
            M[i*4] *= iv; M[i*4+1] *= iv; M[i*4+2] *= iv; M[i*4+3] *= iv;
        }
        #pragma unroll
        for (int j = 0; j < 4; ++j) {
            float cs = M[j] + M[4+j] + M[8+j] + M[12+j] + SK_EPS;
            float iv = 1.f / cs;
            M[j] *= iv; M[4+j] *= iv; M[8+j] *= iv; M[12+j] *= iv;
        }
    }
    float* mx = g_mix + b * 24;
    #pragma unroll
    for (int n = 0; n < 4; ++n) { mx[n] = pre[n]; mx[4 + n] = post[n]; }
    #pragma unroll
    for (int e = 0; e < 16; ++e) mx[8 + e] = M[e];
}

// ---------------------------------------------------------------------------
// K3: big output pass. thread = one float4 group of d for one (b,s).
//   branch_input[b,s,d] = sum_n H[b,s,n,d]*pre[n]
//   H_new[b,s,i,d]      = sum_j H[b,s,j,d]*res[i][j] + post[i]*branch_out[b,s,d]
// ---------------------------------------------------------------------------
__global__ __launch_bounds__(256) void k3_mix(const float4* __restrict__ H4,
                                              const float4* __restrict__ BO4,
                                              float4* __restrict__ out) {
    __shared__ float mix[24];
    const int PERB = SS * D4;                        // 2,097,152 (divisible by 256)
    int idx = blockIdx.x * 256 + threadIdx.x;        // < B*S*D4 = 4,194,304
    int b   = idx / PERB;                            // block-uniform
    int rem = idx - b * PERB;
    int s   = rem / D4;
    int d4  = rem - s * D4;

    if (threadIdx.x < 24) mix[threadIdx.x] = g_mix[b * 24 + threadIdx.x];
    __syncthreads();

    int hbase = ((b*SS + s)*NN) * D4 + d4;
    float4 h0 = H4[hbase];
    float4 h1 = H4[hbase + D4];
    float4 h2 = H4[hbase + 2*D4];
    float4 h3 = H4[hbase + 3*D4];
    float4 bo = BO4[(b*SS + s) * D4 + d4];

    float p0 = mix[0], p1 = mix[1], p2 = mix[2], p3 = mix[3];
    float4 bi;
    bi.x = h0.x*p0 + h1.x*p1 + h2.x*p2 + h3.x*p3;
    bi.y = h0.y*p0 + h1.y*p1 + h2.y*p2 + h3.y*p3;
    bi.z = h0.z*p0 + h1.z*p1 + h2.z*p2 + h3.z*p3;
    bi.w = h0.w*p0 + h1.w*p1 + h2.w*p2 + h3.w*p3;
    out[(b*SS + s) * D4 + d4] = bi;

    float4* outH = out + (size_t)BB * SS * D4;       // H_new region
    #pragma unroll
    for (int i = 0; i < 4; ++i) {
        float r0 = mix[8 + i*4 + 0], r1 = mix[8 + i*4 + 1];
        float r2 = mix[8 + i*4 + 2], r3 = mix[8 + i*4 + 3];
        float po = mix[4 + i];
        float4 o;
        o.x = h0.x*r0 + h1.x*r1 + h2.x*r2 + h3.x*r3 + po*bo.x;
        o.y = h0.y*r0 + h1.y*r1 + h2.y*r2 + h3.y*r3 + po*bo.y;
        o.z = h0.z*r0 + h1.z*r1 + h2.z*r2 + h3.z*r3 + po*bo.z;
        o.w = h0.w*r0 + h1.w*r1 + h2.w*r2 + h3.w*r3 + po*bo.w;
        outH[hbase + i*D4] = o;
    }
}

// ---------------------------------------------------------------------------
extern "C" void kernel_launch(void* const* d_in, const int* in_sizes, int n_in,
                              void* d_out, int out_size) {
    const float* H     = (const float*)d_in[0];
    const float* BO    = (const float*)d_in[1];
    const float* gamma = (const float*)d_in[2];
    const float* beta  = (const float*)d_in[3];
    const float* postb = (const float*)d_in[4];
    const float* preb  = (const float*)d_in[5];
    const float* resb  = (const float*)d_in[6];
    const float* Wpost = (const float*)d_in[7];
    const float* Wpre  = (const float*)d_in[8];
    const float* Wres  = (const float*)d_in[9];
    const float* sp    = (const float*)d_in[10];
    const float* spr   = (const float*)d_in[11];
    const float* sr    = (const float*)d_in[12];
    float* out = (float*)d_out;

    k1_ln_reduce<<<dim3(SCHUNK, NN, BB), 256>>>(H);
    k2a_reduce<<<BND / 256, 256>>>(gamma, beta);
    k2b_dots<<<dim3(24, BB), 256>>>(Wpost, Wpre, Wres);
    k2c_small<<<1, 32>>>(postb, preb, resb, sp, spr, sr);
    k3_mix<<<(BB * SS * D4) / 256, 256>>>((const float4*)H, (const float4*)BO,
                                          (float4*)out);
}

// round 3
// speedup vs baseline: 1.2631x; 1.2631x over previous
#include <cuda_runtime.h>
#include <math.h>

#define BB 2
#define SS 4096
#define NN 4
#define DD 2048
#define ND (NN*DD)            /* 8192  */
#define BND (BB*ND)           /* 16384 */
#define SCHUNK 64
#define ROWS_PER_BLK (SS/SCHUNK)  /* 64 */
#define D4 (DD/4)             /* 512 */
#define LN_EPS 1e-5f
#define SK_EPS 1e-8f

// Scratch (no allocations allowed)
__device__ float g_partial[SCHUNK * BND];   // 4 MB partial LN-mean sums
__device__ float g_hflat[BND];              // H_flat (B, N*D)
__device__ float g_delta[BB * 24];          // raw dots: [post4 | pre4 | res16] per b
__device__ float g_mix[BB * 24];            // final:    [pre4  | post4 | res16] per b

// ---------------------------------------------------------------------------
// K1: per-row LayerNorm + partial sum over S chunk. One block = (chunk, n, b),
// 64 rows of D=2048. Each thread owns 8 elements (two float4 slots).
// Software-pipelined: next row's loads issued before this row's reduction.
// ---------------------------------------------------------------------------
__global__ __launch_bounds__(256) void k1_ln_reduce(const float* __restrict__ H) {
    const int chunk = blockIdx.x, n = blockIdx.y, b = blockIdx.z;
    const int t = threadIdx.x;
    const int warp = t >> 5, lane = t & 31;
    __shared__ float s_w[2][8];
    __shared__ float s_bc[2];

    float a0=0.f,a1=0.f,a2=0.f,a3=0.f,a4=0.f,a5=0.f,a6=0.f,a7=0.f;

    const int s0 = chunk * ROWS_PER_BLK;
    const float4* row = (const float4*)(H + ((size_t)((b*SS + s0)*NN + n)) * DD);
    const int rowstride = NN * D4;   // float4 stride between consecutive s

    float4 v0 = row[t];
    float4 v1 = row[t + 256];

    for (int r = 0; r < ROWS_PER_BLK; ++r) {
        float sm = v0.x+v0.y+v0.z+v0.w + v1.x+v1.y+v1.z+v1.w;
        float sq = v0.x*v0.x+v0.y*v0.y+v0.z*v0.z+v0.w*v0.w
                 + v1.x*v1.x+v1.y*v1.y+v1.z*v1.z+v1.w*v1.w;

        // prefetch next row while we reduce
        float4 n0, n1;
        if (r + 1 < ROWS_PER_BLK) {
            const float4* nrow = row + (size_t)(r + 1) * rowstride;
            n0 = nrow[t];
            n1 = nrow[t + 256];
        }

        #pragma unroll
        for (int o = 16; o; o >>= 1) {
            sm += __shfl_xor_sync(0xffffffffu, sm, o);
            sq += __shfl_xor_sync(0xffffffffu, sq, o);
        }
        if (lane == 0) { s_w[0][warp] = sm; s_w[1][warp] = sq; }
        __syncthreads();
        if (warp == 0) {
            float aa = (lane < 8) ? s_w[0][lane] : 0.f;
            float cc = (lane < 8) ? s_w[1][lane] : 0.f;
            #pragma unroll
            for (int o = 4; o; o >>= 1) {
                aa += __shfl_xor_sync(0xffffffffu, aa, o);
                cc += __shfl_xor_sync(0xffffffffu, cc, o);
            }
            if (lane == 0) {
                float mu  = aa * (1.f / DD);
                float var = cc * (1.f / DD) - mu * mu;
                s_bc[0] = mu;
                s_bc[1] = rsqrtf(var + LN_EPS);
            }
        }
        __syncthreads();
        float mu = s_bc[0], rstd = s_bc[1];
        a0 += (v0.x - mu) * rstd;  a1 += (v0.y - mu) * rstd;
        a2 += (v0.z - mu) * rstd;  a3 += (v0.w - mu) * rstd;
        a4 += (v1.x - mu) * rstd;  a5 += (v1.y - mu) * rstd;
        a6 += (v1.z - mu) * rstd;  a7 += (v1.w - mu) * rstd;
        __syncthreads();           // protect s_bc before next row overwrites
        v0 = n0; v1 = n1;
    }

    float4* p = (float4*)(g_partial + (size_t)chunk * BND + (size_t)(b*NN + n) * DD);
    p[t]       = make_float4(a0, a1, a2, a3);
    p[t + 256] = make_float4(a4, a5, a6, a7);
}

// ---------------------------------------------------------------------------
// K2a: reduce the 64 chunk partials -> H_flat, apply gamma/beta and /S.
// ---------------------------------------------------------------------------
__global__ __launch_bounds__(256) void k2a_reduce(const float* __restrict__ gamma,
                                                  const float* __restrict__ beta) {
    int o = blockIdx.x * 256 + threadIdx.x;   // [0, BND)
    float sum = 0.f;
    #pragma unroll 8
    for (int c = 0; c < SCHUNK; ++c) sum += g_partial[(size_t)c * BND + o];
    int d = o & (DD - 1);
    g_hflat[o] = gamma[d] * (sum * (1.f / SS)) + beta[d];
}

// ---------------------------------------------------------------------------
// K2b: 48 dot products of length 8192. block = (row r in [0,24), batch b).
// ---------------------------------------------------------------------------
__global__ __launch_bounds__(256) void k2b_dots(const float* __restrict__ Wpost,
                                                const float* __restrict__ Wpre,
                                                const float* __restrict__ Wres) {
    const int r = blockIdx.x, b = blockIdx.y;
    const float* w = (r < 4)  ? (Wpost + (size_t)r * ND)
                   : (r < 8)  ? (Wpre  + (size_t)(r - 4) * ND)
                              : (Wres  + (size_t)(r - 8) * ND);
    const float* h = g_hflat + b * ND;
    float sum = 0.f;
    for (int k = threadIdx.x; k < ND; k += 256) sum += h[k] * w[k];

    __shared__ float s_w[8];
    int warp = threadIdx.x >> 5, lane = threadIdx.x & 31;
    #pragma unroll
    for (int o = 16; o; o >>= 1) sum += __shfl_xor_sync(0xffffffffu, sum, o);
    if (lane == 0) s_w[warp] = sum;
    __syncthreads();
    if (threadIdx.x == 0) {
        float t = 0.f;
        #pragma unroll
        for (int i = 0; i < 8; ++i) t += s_w[i];
        g_delta[b * 24 + r] = t;
    }
}

// ---------------------------------------------------------------------------
// K2c: sigmoid gates + H_pre normalize + 4x4 Sinkhorn (20 iters). 1 thread/b.
// Fast-math intrinsics: the 160 serialized divisions were 19.7us as IEEE div.
// ---------------------------------------------------------------------------
__global__ void k2c_small(const float* __restrict__ postb,
                          const float* __restrict__ preb,
                          const float* __restrict__ resb,
                          const float* __restrict__ sp,
                          const float* __restrict__ spr,
                          const float* __restrict__ sr) {
    int b = threadIdx.x;
    if (b >= BB) return;
    const float* dlt = g_delta + b * 24;
    float scp = sp[0], scq = spr[0], scr = sr[0];

    float pre[4], post[4], M[16];
    float psum = 0.f;
    #pragma unroll
    for (int n = 0; n < 4; ++n) {
        post[n] = __fdividef(1.f, 1.f + __expf(-(postb[n] + dlt[n]     * scp)));
        float pv = __fdividef(1.f, 1.f + __expf(-(preb[n] + dlt[4 + n] * scq)));
        pre[n] = pv; psum += pv;
    }
    float inv = __fdividef(1.f, psum + SK_EPS);
    #pragma unroll
    for (int n = 0; n < 4; ++n) pre[n] *= inv;

    #pragma unroll
    for (int e = 0; e < 16; ++e) M[e] = __expf(resb[e] + dlt[8 + e] * scr);

    for (int it = 0; it < 20; ++it) {
        #pragma unroll
        for (int i = 0; i < 4; ++i) {
            float rs = M[i*4] + M[i*4+1] + M[i*4+2] + M[i*4+3] + SK_EPS;
            float iv = __fdividef(1.f, rs);
            M[i*4] *= iv; M[i*4+1] *= iv; M[i*4+2] *= iv; M[i*4+3] *= iv;
        }
        #pragma unroll
        for (int j = 0; j < 4; ++j) {
            float cs = M[j] + M[4+j] + M[8+j] + M[12+j] + SK_EPS;
            float iv = __fdividef(1.f, cs);
            M[j] *= iv; M[4+j] *= iv; M[8+j] *= iv; M[12+j] *= iv;
        }
    }
    float* mx = g_mix + b * 24;
    #pragma unroll
    for (int n = 0; n < 4; ++n) { mx[n] = pre[n]; mx[4 + n] = post[n]; }
    #pragma unroll
    for (int e = 0; e < 16; ++e) mx[8 + e] = M[e];
}

// ---------------------------------------------------------------------------
// K3: big output pass. thread = one float4 group of d for one (b,s).
//   branch_input[b,s,d] = sum_n H[b,s,n,d]*pre[n]
//   H_new[b,s,i,d]      = sum_j H[b,s,j,d]*res[i][j] + post[i]*branch_out[b,s,d]
// ---------------------------------------------------------------------------
__global__ __launch_bounds__(256) void k3_mix(const float4* __restrict__ H4,
                                              const float4* __restrict__ BO4,
                                              float4* __restrict__ out) {
    __shared__ float mix[24];
    const int PERB = SS * D4;                        // 2,097,152 (divisible by 256)
    int idx = blockIdx.x * 256 + threadIdx.x;        // < B*S*D4 = 4,194,304
    int b   = idx / PERB;                            // block-uniform
    int rem = idx - b * PERB;
    int s   = rem / D4;
    int d4  = rem - s * D4;

    if (threadIdx.x < 24) mix[threadIdx.x] = g_mix[b * 24 + threadIdx.x];
    __syncthreads();

    int hbase = ((b*SS + s)*NN) * D4 + d4;
    float4 h0 = H4[hbase];
    float4 h1 = H4[hbase + D4];
    float4 h2 = H4[hbase + 2*D4];
    float4 h3 = H4[hbase + 3*D4];
    float4 bo = BO4[(b*SS + s) * D4 + d4];

    float p0 = mix[0], p1 = mix[1], p2 = mix[2], p3 = mix[3];
    float4 bi;
    bi.x = h0.x*p0 + h1.x*p1 + h2.x*p2 + h3.x*p3;
    bi.y = h0.y*p0 + h1.y*p1 + h2.y*p2 + h3.y*p3;
    bi.z = h0.z*p0 + h1.z*p1 + h2.z*p2 + h3.z*p3;
    bi.w = h0.w*p0 + h1.w*p1 + h2.w*p2 + h3.w*p3;
    out[(b*SS + s) * D4 + d4] = bi;

    float4* outH = out + (size_t)BB * SS * D4;       // H_new region
    #pragma unroll
    for (int i = 0; i < 4; ++i) {
        float r0 = mix[8 + i*4 + 0], r1 = mix[8 + i*4 + 1];
        float r2 = mix[8 + i*4 + 2], r3 = mix[8 + i*4 + 3];
        float po = mix[4 + i];
        float4 o;
        o.x = h0.x*r0 + h1.x*r1 + h2.x*r2 + h3.x*r3 + po*bo.x;
        o.y = h0.y*r0 + h1.y*r1 + h2.y*r2 + h3.y*r3 + po*bo.y;
        o.z = h0.z*r0 + h1.z*r1 + h2.z*r2 + h3.z*r3 + po*bo.z;
        o.w = h0.w*r0 + h1.w*r1 + h2.w*r2 + h3.w*r3 + po*bo.w;
        outH[hbase + i*D4] = o;
    }
}

// ---------------------------------------------------------------------------
extern "C" void kernel_launch(void* const* d_in, const int* in_sizes, int n_in,
                              void* d_out, int out_size) {
    const float* H     = (const float*)d_in[0];
    const float* BO    = (const float*)d_in[1];
    const float* gamma = (const float*)d_in[2];
    const float* beta  = (const float*)d_in[3];
    const float* postb = (const float*)d_in[4];
    const float* preb  = (const float*)d_in[5];
    const float* resb  = (const float*)d_in[6];
    const float* Wpost = (const float*)d_in[7];
    const float* Wpre  = (const float*)d_in[8];
    const float* Wres  = (const float*)d_in[9];
    const float* sp    = (const float*)d_in[10];
    const float* spr   = (const float*)d_in[11];
    const float* sr    = (const float*)d_in[12];
    float* out = (float*)d_out;

    k1_ln_reduce<<<dim3(SCHUNK, NN, BB), 256>>>(H);
    k2a_reduce<<<BND / 256, 256>>>(gamma, beta);
    k2b_dots<<<dim3(24, BB), 256>>>(Wpost, Wpre, Wres);
    k2c_small<<<1, 32>>>(postb, preb, resb, sp, spr, sr);
    k3_mix<<<(BB * SS * D4) / 256, 256>>>((const float4*)H, (const float4*)BO,
                                          (float4*)out);
}

// round 5
// speedup vs baseline: 1.2787x; 1.0123x over previous
#include <cuda_runtime.h>
#include <math.h>

#define BB 2
#define SS 4096
#define NN 4
#define DD 2048
#define ND (NN*DD)            /* 8192  */
#define BND (BB*ND)           /* 16384 */
#define SCHUNK 64
#define ROWS_PER_BLK (SS/SCHUNK)  /* 64 */
#define D4 (DD/4)             /* 512 */
#define LN_EPS 1e-5f
#define SK_EPS 1e-8f
#define K2_BLOCKS 64

// Scratch (no allocations allowed)
__device__ float g_partial[SCHUNK * BND];   // 4 MB partial LN-mean sums
__device__ float g_hflat[BND];              // H_flat (B, N*D)
__device__ float g_delta[BB * 24];          // raw dots: [post4 | pre4 | res16] per b
__device__ float g_mix[BB * 24];            // final:    [pre4  | post4 | res16] per b

// Sense-reversing grid barrier state (persists across graph replays; flag
// toggles, counter self-resets -> idempotent).
__device__ unsigned g_bar_count = 0;
__device__ volatile unsigned g_bar_flag = 0;

__device__ __forceinline__ void grid_barrier(unsigned nblocks, unsigned& sense) {
    __syncthreads();
    if (threadIdx.x == 0) {
        __threadfence();
        unsigned t = atomicAdd(&g_bar_count, 1u);
        if (t == nblocks - 1) {
            g_bar_count = 0;
            __threadfence();
            g_bar_flag = sense ^ 1u;          // release
        } else {
            while (g_bar_flag == sense) { }   // all blocks resident: safe spin
            __threadfence();
        }
    }
    __syncthreads();
    sense ^= 1u;
}

// ---------------------------------------------------------------------------
// K1: per-row LayerNorm + partial sum over S chunk. One block = (chunk, n, b),
// 64 rows of D=2048. Each thread owns 8 elements (two float4 slots).
// Software-pipelined: next row's loads issued before this row's reduction.
// ---------------------------------------------------------------------------
__global__ __launch_bounds__(256) void k1_ln_reduce(const float* __restrict__ H) {
    const int chunk = blockIdx.x, n = blockIdx.y, b = blockIdx.z;
    const int t = threadIdx.x;
    const int warp = t >> 5, lane = t & 31;
    __shared__ float s_w[2][8];
    __shared__ float s_bc[2];

    float a0=0.f,a1=0.f,a2=0.f,a3=0.f,a4=0.f,a5=0.f,a6=0.f,a7=0.f;

    const int s0 = chunk * ROWS_PER_BLK;
    const float4* row = (const float4*)(H + ((size_t)((b*SS + s0)*NN + n)) * DD);
    const int rowstride = NN * D4;   // float4 stride between consecutive s

    float4 v0 = __ldcs(row + t);
    float4 v1 = __ldcs(row + t + 256);

    for (int r = 0; r < ROWS_PER_BLK; ++r) {
        float sm = v0.x+v0.y+v0.z+v0.w + v1.x+v1.y+v1.z+v1.w;
        float sq = v0.x*v0.x+v0.y*v0.y+v0.z*v0.z+v0.w*v0.w
                 + v1.x*v1.x+v1.y*v1.y+v1.z*v1.z+v1.w*v1.w;

        // prefetch next row while we reduce
        float4 n0, n1;
        if (r + 1 < ROWS_PER_BLK) {
            const float4* nrow = row + (size_t)(r + 1) * rowstride;
            n0 = __ldcs(nrow + t);
            n1 = __ldcs(nrow + t + 256);
        }

        #pragma unroll
        for (int o = 16; o; o >>= 1) {
            sm += __shfl_xor_sync(0xffffffffu, sm, o);
            sq += __shfl_xor_sync(0xffffffffu, sq, o);
        }
        if (lane == 0) { s_w[0][warp] = sm; s_w[1][warp] = sq; }
        __syncthreads();
        if (warp == 0) {
            float aa = (lane < 8) ? s_w[0][lane] : 0.f;
            float cc = (lane < 8) ? s_w[1][lane] : 0.f;
            #pragma unroll
            for (int o = 4; o; o >>= 1) {
                aa += __shfl_xor_sync(0xffffffffu, aa, o);
                cc += __shfl_xor_sync(0xffffffffu, cc, o);
            }
            if (lane == 0) {
                float mu  = aa * (1.f / DD);
                float var = cc * (1.f / DD) - mu * mu;
                s_bc[0] = mu;
                s_bc[1] = rsqrtf(var + LN_EPS);
            }
        }
        __syncthreads();
        float mu = s_bc[0], rstd = s_bc[1];
        a0 += (v0.x - mu) * rstd;  a1 += (v0.y - mu) * rstd;
        a2 += (v0.z - mu) * rstd;  a3 += (v0.w - mu) * rstd;
        a4 += (v1.x - mu) * rstd;  a5 += (v1.y - mu) * rstd;
        a6 += (v1.z - mu) * rstd;  a7 += (v1.w - mu) * rstd;
        __syncthreads();           // protect s_bc before next row overwrites
        v0 = n0; v1 = n1;
    }

    float4* p = (float4*)(g_partial + (size_t)chunk * BND + (size_t)(b*NN + n) * DD);
    p[t]       = make_float4(a0, a1, a2, a3);
    p[t + 256] = make_float4(a4, a5, a6, a7);
}

// ---------------------------------------------------------------------------
// K2 fused: phase A (partial reduce -> hflat), phase B (48 dots),
// phase C (gates + parallel 4x4 Sinkhorn). One launch, grid barriers between.
// Grid: 64 blocks x 256 threads (all resident on 148 SMs).
// ---------------------------------------------------------------------------
__global__ __launch_bounds__(256) void k2_fused(
        const float* __restrict__ gamma, const float* __restrict__ beta,
        const float* __restrict__ Wpost, const float* __restrict__ Wpre,
        const float* __restrict__ Wres,
        const float* __restrict__ postb, const float* __restrict__ preb,
        const float* __restrict__ resb,
        const float* __restrict__ sp, const float* __restrict__ spr,
        const float* __restrict__ sr) {
    unsigned sense = g_bar_flag;   // stable: flag can't change before everyone arrives

    // ---- Phase A: reduce 64 chunk partials -> hflat (one output per thread)
    {
        int o = blockIdx.x * 256 + threadIdx.x;   // [0, BND)
        float sum = 0.f;
        #pragma unroll 8
        for (int c = 0; c < SCHUNK; ++c) sum += g_partial[(size_t)c * BND + o];
        int d = o & (DD - 1);
        g_hflat[o] = gamma[d] * (sum * (1.f / SS)) + beta[d];
    }

    grid_barrier(K2_BLOCKS, sense);

    // ---- Phase B: blocks 0..47 each compute one dot (r, b)
    if (blockIdx.x < 48) {
        const int r = blockIdx.x % 24, b = blockIdx.x / 24;
        const float* w = (r < 4)  ? (Wpost + (size_t)r * ND)
                       : (r < 8)  ? (Wpre  + (size_t)(r - 4) * ND)
                                  : (Wres  + (size_t)(r - 8) * ND);
        const float* h = g_hflat + b * ND;
        float sum = 0.f;
        for (int k = threadIdx.x; k < ND; k += 256) sum += h[k] * w[k];

        __shared__ float s_w[8];
        int warp = threadIdx.x >> 5, lane = threadIdx.x & 31;
        #pragma unroll
        for (int o = 16; o; o >>= 1) sum += __shfl_xor_sync(0xffffffffu, sum, o);
        if (lane == 0) s_w[warp] = sum;
        __syncthreads();
        if (threadIdx.x == 0) {
            float t = 0.f;
            #pragma unroll
            for (int i = 0; i < 8; ++i) t += s_w[i];
            g_delta[b * 24 + r] = t;
        }
    }

    grid_barrier(K2_BLOCKS, sense);

    // ---- Phase C: block 0, threads 0..7. thread t: b = t>>2, row/gate n = t&3.
    if (blockIdx.x == 0 && threadIdx.x < 8) {
        const int t = threadIdx.x;
        const int b = t >> 2, n = t & 3;
        const float* dlt = g_delta + b * 24;
        const float scp = sp[0], scq = spr[0], scr = sr[0];
        const unsigned grp = 0xFu << (b * 4);  // active mask within 4-lane group

        // gates
        float post = __fdividef(1.f, 1.f + __expf(-(postb[n] + dlt[n]     * scp)));
        float pre  = __fdividef(1.f, 1.f + __expf(-(preb[n] + dlt[4 + n] * scq)));
        float psum = pre;
        psum += __shfl_xor_sync(grp, psum, 1);
        psum += __shfl_xor_sync(grp, psum, 2);
        pre *= __fdividef(1.f, psum + SK_EPS);

        // Sinkhorn: thread owns row n of M (4 values)
        float m0 = __expf(resb[n*4 + 0] + dlt[8 + n*4 + 0] * scr);
        float m1 = __expf(resb[n*4 + 1] + dlt[8 + n*4 + 1] * scr);
        float m2 = __expf(resb[n*4 + 2] + dlt[8 + n*4 + 2] * scr);
        float m3 = __expf(resb[n*4 + 3] + dlt[8 + n*4 + 3] * scr);

        #pragma unroll 4
        for (int it = 0; it < 20; ++it) {
            // row normalize (local)
            float iv = __fdividef(1.f, m0 + m1 + m2 + m3 + SK_EPS);
            m0 *= iv; m1 *= iv; m2 *= iv; m3 *= iv;
            // column sums across the 4 threads of this batch
            float c0 = m0, c1 = m1, c2 = m2, c3 = m3;
            c0 += __shfl_xor_sync(grp, c0, 1);
            c1 += __shfl_xor_sync(grp, c1, 1);
            c2 += __shfl_xor_sync(grp, c2, 1);
            c3 += __shfl_xor_sync(grp, c3, 1);
            c0 += __shfl_xor_sync(grp, c0, 2);
            c1 += __shfl_xor_sync(grp, c1, 2);
            c2 += __shfl_xor_sync(grp, c2, 2);
            c3 += __shfl_xor_sync(grp, c3, 2);
            m0 *= __fdividef(1.f, c0 + SK_EPS);
            m1 *= __fdividef(1.f, c1 + SK_EPS);
            m2 *= __fdividef(1.f, c2 + SK_EPS);
            m3 *= __fdividef(1.f, c3 + SK_EPS);
        }

        float* mx = g_mix + b * 24;
        mx[n]     = pre;
        mx[4 + n] = post;
        mx[8 + n*4 + 0] = m0;
        mx[8 + n*4 + 1] = m1;
        mx[8 + n*4 + 2] = m2;
        mx[8 + n*4 + 3] = m3;
    }
}

// ---------------------------------------------------------------------------
// K3: big output pass. thread = one float4 group of d for one (b,s).
//   branch_input[b,s,d] = sum_n H[b,s,n,d]*pre[n]
//   H_new[b,s,i,d]      = sum_j H[b,s,j,d]*res[i][j] + post[i]*branch_out[b,s,d]
// ---------------------------------------------------------------------------
__global__ __launch_bounds__(256) void k3_mix(const float4* __restrict__ H4,
                                              const float4* __restrict__ BO4,
                                              float4* __restrict__ out) {
    __shared__ float mix[24];
    const int PERB = SS * D4;                        // 2,097,152 (divisible by 256)
    int idx = blockIdx.x * 256 + threadIdx.x;        // < B*S*D4 = 4,194,304
    int b   = idx / PERB;                            // block-uniform
    int rem = idx - b * PERB;
    int s   = rem / D4;
    int d4  = rem - s * D4;

    if (threadIdx.x < 24) mix[threadIdx.x] = g_mix[b * 24 + threadIdx.x];
    __syncthreads();

    int hbase = ((b*SS + s)*NN) * D4 + d4;
    float4 h0 = __ldcs(H4 + hbase);
    float4 h1 = __ldcs(H4 + hbase + D4);
    float4 h2 = __ldcs(H4 + hbase + 2*D4);
    float4 h3 = __ldcs(H4 + hbase + 3*D4);
    float4 bo = __ldcs(BO4 + (b*SS + s) * D4 + d4);

    float p0 = mix[0], p1 = mix[1], p2 = mix[2], p3 = mix[3];
    float4 bi;
    bi.x = h0.x*p0 + h1.x*p1 + h2.x*p2 + h3.x*p3;
    bi.y = h0.y*p0 + h1.y*p1 + h2.y*p2 + h3.y*p3;
    bi.z = h0.z*p0 + h1.z*p1 + h2.z*p2 + h3.z*p3;
    bi.w = h0.w*p0 + h1.w*p1 + h2.w*p2 + h3.w*p3;
    __stcs(out + (b*SS + s) * D4 + d4, bi);

    float4* outH = out + (size_t)BB * SS * D4;       // H_new region
    #pragma unroll
    for (int i = 0; i < 4; ++i) {
        float r0 = mix[8 + i*4 + 0], r1 = mix[8 + i*4 + 1];
        float r2 = mix[8 + i*4 + 2], r3 = mix[8 + i*4 + 3];
        float po = mix[4 + i];
        float4 o;
        o.x = h0.x*r0 + h1.x*r1 + h2.x*r2 + h3.x*r3 + po*bo.x;
        o.y = h0.y*r0 + h1.y*r1 + h2.y*r2 + h3.y*r3 + po*bo.y;
        o.z = h0.z*r0 + h1.z*r1 + h2.z*r2 + h3.z*r3 + po*bo.z;
        o.w = h0.w*r0 + h1.w*r1 + h2.w*r2 + h3.w*r3 + po*bo.w;
        __stcs(outH + hbase + i*D4, o);
    }
}

// ---------------------------------------------------------------------------
extern "C" void kernel_launch(void* const* d_in, const int* in_sizes, int n_in,
                              void* d_out, int out_size) {
    const float* H     = (const float*)d_in[0];
    const float* BO    = (const float*)d_in[1];
    const float* gamma = (const float*)d_in[2];
    const float* beta  = (const float*)d_in[3];
    const float* postb = (const float*)d_in[4];
    const float* preb  = (const float*)d_in[5];
    const float* resb  = (const float*)d_in[6];
    const float* Wpost = (const float*)d_in[7];
    const float* Wpre  = (const float*)d_in[8];
    const float* Wres  = (const float*)d_in[9];
    const float* sp    = (const float*)d_in[10];
    const float* spr   = (const float*)d_in[11];
    const float* sr    = (const float*)d_in[12];
    float* out = (float*)d_out;

    k1_ln_reduce<<<dim3(SCHUNK, NN, BB), 256>>>(H);
    k2_fused<<<K2_BLOCKS, 256>>>(gamma, beta, Wpost, Wpre, Wres,
                                 postb, preb, resb, sp, spr, sr);
    k3_mix<<<(BB * SS * D4) / 256, 256>>>((const float4*)H, (const float4*)BO,
                                          (float4*)out);
}